// round 8
// baseline (speedup 1.0000x reference)
#include <cuda_runtime.h>
#include <cstdint>
#include <cstddef>

#define N_REC   256
#define T_STEPS 1000
#define NI      3
#define NO      3
#define ALPHA_F 0.2f
#define LEAK_F  0.8f
#define NOISE_SCALE_F 0.03162277660168379f

#define THREADS 512
#define WREG4   12          // float4s of W per thread in registers (48 floats)
#define WSM4    20          // float4s of W per thread in smem (80 floats)
#define WROW    84          // smem W row stride in floats (21 x 16B, odd -> conflict-free)
// floats: rbuf 1024 | wsh 512*84=43008 | wout 768 | wb 4 | part 512
#define SMEM_FLOATS (1024 + 512 * WROW + 768 + 4 + 512)
#define SMEM_BYTES  (SMEM_FLOATS * 4)

__device__ __forceinline__ unsigned long long pk2(float x, float y) {
    unsigned long long r;
    asm("mov.b64 %0, {%1, %2};" : "=l"(r) : "f"(x), "f"(y));
    return r;
}
__device__ __forceinline__ void upk2(unsigned long long v, float& x, float& y) {
    asm("mov.b64 {%0, %1}, %2;" : "=f"(x), "=f"(y) : "l"(v));
}
// Blackwell packed dual-fp32 FMA (sm_100+).
__device__ __forceinline__ unsigned long long ffma2(unsigned long long a,
                                                    unsigned long long b,
                                                    unsigned long long c) {
    unsigned long long d;
    asm("fma.rn.f32x2 %0, %1, %2, %3;" : "=l"(d) : "l"(a), "l"(b), "l"(c));
    return d;
}

// Output projection for one batch's step, one warp, overlapped with the
// h=0 update phase. rb = rbuf slice (256 floats).
__device__ __forceinline__ void emit_out(const float* __restrict__ rb,
                                         const float* __restrict__ wout_s,
                                         const float* __restrict__ wb3,
                                         float* __restrict__ out,
                                         int bidx, int tstore, int lane)
{
    const float4* rv = reinterpret_cast<const float4*>(rb);
    float4 ra = rv[lane];
    float4 rc = rv[32 + lane];
    const float4* w0 = reinterpret_cast<const float4*>(wout_s);
    const float4* w1 = reinterpret_cast<const float4*>(wout_s + 256);
    const float4* w2 = reinterpret_cast<const float4*>(wout_s + 512);
    float4 a0 = w0[lane], c0 = w0[32 + lane];
    float4 a1 = w1[lane], c1 = w1[32 + lane];
    float4 a2 = w2[lane], c2 = w2[32 + lane];

    float p0 = ra.x*a0.x + ra.y*a0.y + ra.z*a0.z + ra.w*a0.w
             + rc.x*c0.x + rc.y*c0.y + rc.z*c0.z + rc.w*c0.w;
    float p1 = ra.x*a1.x + ra.y*a1.y + ra.z*a1.z + ra.w*a1.w
             + rc.x*c1.x + rc.y*c1.y + rc.z*c1.z + rc.w*c1.w;
    float p2 = ra.x*a2.x + ra.y*a2.y + ra.z*a2.z + ra.w*a2.w
             + rc.x*c2.x + rc.y*c2.y + rc.z*c2.z + rc.w*c2.w;

    #pragma unroll
    for (int off = 16; off > 0; off >>= 1) {
        p0 += __shfl_xor_sync(0xffffffffu, p0, off);
        p1 += __shfl_xor_sync(0xffffffffu, p1, off);
        p2 += __shfl_xor_sync(0xffffffffu, p2, off);
    }
    if (lane == 0) {
        float* o = out + ((size_t)bidx * T_STEPS + tstore) * NO;
        o[0] = p0 + wb3[0];
        o[1] = p1 + wb3[1];
        o[2] = p2 + wb3[2];
    }
}

__global__ __launch_bounds__(THREADS, 1)
void rnn_persistent_kernel(const float* __restrict__ x,
                           const float* __restrict__ noise,
                           const float* __restrict__ W_in,
                           const float* __restrict__ W_rec,
                           const float* __restrict__ W_out_w,
                           const float* __restrict__ W_out_b,
                           const float* __restrict__ bias,
                           float* __restrict__ out)
{
    extern __shared__ float smem[];
    float*  rbuf   = smem;                     // [2 buf][2 batch][256]
    float*  wsh    = smem + 1024;              // [512 logical rows][WROW]
    float*  wout_s = wsh + 512 * WROW;         // [3][256]
    float*  wb3    = wout_s + 768;             // [3] (+1 pad)
    float2* part   = reinterpret_cast<float2*>(wb3 + 4);  // [256]

    const int tid  = threadIdx.x;
    const int lane = tid & 31;
    const int warp = tid >> 5;
    const int n    = tid & 255;                // row / neuron
    const int h    = tid >> 8;                 // k-half: 0 -> [0,128), 1 -> [128,256)
    const int b0   = blockIdx.x * 2;

    // ---- W row n, k in [h*128, h*128+48): 48 floats -> 24 packed regs ----
    unsigned long long w[2 * WREG4];
    {
        const float4* wr4 =
            reinterpret_cast<const float4*>(W_rec + (size_t)n * N_REC + h * 128);
        #pragma unroll
        for (int i = 0; i < WREG4; i++) {
            float4 v = wr4[i];
            w[2 * i]     = pk2(v.x, v.y);
            w[2 * i + 1] = pk2(v.z, v.w);
        }
        // k in [h*128+48, h*128+128): 80 floats -> SMEM padded row
        float4* wrow = reinterpret_cast<float4*>(wsh + (size_t)(h * 256 + n) * WROW);
        #pragma unroll
        for (int i = 0; i < WSM4; i++) wrow[i] = wr4[WREG4 + i];
    }
    // ---- W_out / bias -> SMEM ----
    for (int idx = tid; idx < NO * N_REC; idx += THREADS) wout_s[idx] = W_out_w[idx];
    if (tid < NO) wb3[tid] = W_out_b[tid];

    // per-row constants, needed only by h=0 (update owners)
    const float wi0 = W_in[n * 3 + 0], wi1 = W_in[n * 3 + 1], wi2 = W_in[n * 3 + 2];
    const float bi  = bias[n];

    // initial state r = 0 in buffer 0 (512 floats, one per thread)
    rbuf[tid] = 0.f;

    const float* nzp0 = noise + (size_t)b0 * T_STEPS * N_REC + n;
    const float* nzp1 = nzp0 + (size_t)T_STEPS * N_REC;
    const float* xp0  = x + (size_t)b0 * T_STEPS * NI;
    const float* xp1  = xp0 + (size_t)T_STEPS * NI;

    float rold0 = 0.f, rold1 = 0.f;

    __syncthreads();

    const float4* wsv =
        reinterpret_cast<const float4*>(wsh + (size_t)(h * 256 + n) * WROW);

    for (int t = 0; t < T_STEPS; t++) {
        const int cur = t & 1, nxt = cur ^ 1;

        float nz0 = 0.f, nz1 = 0.f, x00 = 0.f, x01 = 0.f, x02 = 0.f,
              x10 = 0.f, x11 = 0.f, x12 = 0.f;
        if (h == 0) {   // prefetch drive inputs (used after the dot phase)
            nz0 = __ldg(nzp0 + t * N_REC);
            nz1 = __ldg(nzp1 + t * N_REC);
            x00 = __ldg(xp0 + t * 3 + 0);
            x01 = __ldg(xp0 + t * 3 + 1);
            x02 = __ldg(xp0 + t * 3 + 2);
            x10 = __ldg(xp1 + t * 3 + 0);
            x11 = __ldg(xp1 + t * 3 + 1);
            x12 = __ldg(xp1 + t * 3 + 2);
        }

        // ---- half-row dot: k in [h*128, h*128+128), both batches ----
        // reg-W covers first 48 k, smem-W the remaining 80; fused/interleaved.
        const float4* rb0 = reinterpret_cast<const float4*>(rbuf + cur * 512 + h * 128);
        const float4* rb1 = rb0 + 64;  // +256 floats = batch 1

        unsigned long long A0 = 0, B0 = 0, A1 = 0, B1 = 0;
        #pragma unroll
        for (int i = 0; i < WSM4; i++) {
            float4 wv = wsv[i];                       // smem W chunk
            float4 q0 = rb0[WREG4 + i];               // r b0 (broadcast)
            float4 q1 = rb1[WREG4 + i];               // r b1
            unsigned long long wp0 = pk2(wv.x, wv.y);
            unsigned long long wp1 = pk2(wv.z, wv.w);
            A0 = ffma2(wp0, pk2(q0.x, q0.y), A0);
            A0 = ffma2(wp1, pk2(q0.z, q0.w), A0);
            A1 = ffma2(wp0, pk2(q1.x, q1.y), A1);
            A1 = ffma2(wp1, pk2(q1.z, q1.w), A1);
            if (i < WREG4) {                          // reg-W chunk interleaved
                float4 p0 = rb0[i];
                float4 p1 = rb1[i];
                B0 = ffma2(w[2 * i],     pk2(p0.x, p0.y), B0);
                B0 = ffma2(w[2 * i + 1], pk2(p0.z, p0.w), B0);
                B1 = ffma2(w[2 * i],     pk2(p1.x, p1.y), B1);
                B1 = ffma2(w[2 * i + 1], pk2(p1.z, p1.w), B1);
            }
        }
        float e0, e1, e2, e3;
        upk2(A0, e0, e1); upk2(B0, e2, e3);
        const float d0 = (e0 + e1) + (e2 + e3);
        upk2(A1, e0, e1); upk2(B1, e2, e3);
        const float d1 = (e0 + e1) + (e2 + e3);

        if (h == 1) part[n] = make_float2(d0, d1);
        __syncthreads();

        if (h == 0) {
            const float2 pp = part[n];
            const float dot0 = d0 + pp.x;
            const float dot1 = d1 + pp.y;
            const float u0 = fmaf(NOISE_SCALE_F, nz0, bi) + x00*wi0 + x01*wi1 + x02*wi2;
            const float u1 = fmaf(NOISE_SCALE_F, nz1, bi) + x10*wi0 + x11*wi1 + x12*wi2;
            const float rn0 = LEAK_F * rold0 + ALPHA_F * fmaxf(dot0 + u0, 0.f);
            const float rn1 = LEAK_F * rold1 + ALPHA_F * fmaxf(dot1 + u1, 0.f);
            rold0 = rn0; rold1 = rn1;
            rbuf[nxt * 512 + n]       = rn0;
            rbuf[nxt * 512 + 256 + n] = rn1;
        } else if (t > 0 && (warp == 8 || warp == 9)) {
            // h=1 warps are idle during the update window: emit output t-1
            emit_out(rbuf + cur * 512 + (warp - 8) * 256, wout_s, wb3, out,
                     b0 + (warp - 8), t - 1, lane);
        }
        __syncthreads();
    }

    // final output t = T-1: final r is in buffer (T_STEPS & 1) = 0
    if (warp == 8 || warp == 9) {
        emit_out(rbuf + (T_STEPS & 1) * 512 + (warp - 8) * 256, wout_s, wb3, out,
                 b0 + (warp - 8), T_STEPS - 1, lane);
    }
}

extern "C" void kernel_launch(void* const* d_in, const int* in_sizes, int n_in,
                              void* d_out, int out_size)
{
    const float* x       = (const float*)d_in[0];
    const float* noise   = (const float*)d_in[1];
    const float* W_in    = (const float*)d_in[2];
    const float* W_rec   = (const float*)d_in[3];
    const float* W_out_w = (const float*)d_in[4];
    const float* W_out_b = (const float*)d_in[5];
    const float* bias    = (const float*)d_in[6];
    float* out = (float*)d_out;

    static bool attr_done = false;
    if (!attr_done) {
        (void)cudaFuncSetAttribute(rnn_persistent_kernel,
                                   cudaFuncAttributeMaxDynamicSharedMemorySize,
                                   SMEM_BYTES);
        attr_done = true;
    }

    rnn_persistent_kernel<<<128, THREADS, SMEM_BYTES>>>(
        x, noise, W_in, W_rec, W_out_w, W_out_b, bias, out);
}